// round 1
// baseline (speedup 1.0000x reference)
#include <cuda_runtime.h>
#include <math.h>

// Problem constants
#define VD   256          // embedding dim D
#define LL   32           // tokens per sequence
#define MM   4096         // mems rows
#define CC   4096         // cands rows
#define ROWS (MM + 1)     // mems_enc rows (mems + xs)
#define EPS  1e-8f
#define NPART 64          // partial blocks for att @ mems_enc

// Scratch (allocation-free: __device__ globals)
__device__ float g_mems_enc[ROWS * VD];   // rows 0..M-1 = encode(mems), row M = xs_emb
__device__ float g_cos[ROWS];
__device__ float g_att[ROWS];
__device__ float g_partial[NPART * VD];
__device__ float g_lhs[VD];

// ---------------------------------------------------------------------------
// Kernel 1: encode all sequences.
// Grid: MM (mems) + 1 (xs) + 1 (ys) + CC (cands) blocks, 256 threads each.
// Each block: load 32 token ids, w = freqs[tok], w /= ||w||2, then
// out[d] = sum_l w[l] * lt[tok[l]*256 + d].
// ---------------------------------------------------------------------------
__global__ void encode_kernel(const int* __restrict__ xs,
                              const int* __restrict__ mems,
                              const int* __restrict__ ys,
                              const int* __restrict__ cands,
                              const float* __restrict__ lt,
                              const float* __restrict__ freqs,
                              float* __restrict__ out_ys /* d_out + (C+1)*D */)
{
    __shared__ int   toks[LL];
    __shared__ float ws[LL];

    const int s = blockIdx.x;
    const int t = threadIdx.x;

    // Resolve source tokens and destination pointer
    const int* src;
    float* dst;
    if (s < MM) {                       // mems row s
        src = mems + (size_t)s * LL;
        dst = g_mems_enc + (size_t)s * VD;
    } else if (s == MM) {               // xs -> row M of mems_enc
        src = xs;
        dst = g_mems_enc + (size_t)MM * VD;
    } else if (s == MM + 1) {           // ys -> ys_out row 0
        src = ys;
        dst = out_ys;
    } else {                            // cand c -> ys_out row 1+c
        const int c = s - (MM + 2);
        src = cands + (size_t)c * LL;
        dst = out_ys + (size_t)(1 + c) * VD;
    }

    if (t < LL) {
        int tok = src[t];
        toks[t] = tok;
        ws[t] = freqs[tok];
    }
    __syncthreads();

    // Normalize weights: done redundantly by warp 0, broadcast through smem
    if (t < 32) {
        float w = ws[t];
        float sq = w * w;
        #pragma unroll
        for (int o = 16; o; o >>= 1) sq += __shfl_xor_sync(0xFFFFFFFFu, sq, o);
        float inv = rsqrtf(sq);
        ws[t] = w * inv;
    }
    __syncthreads();

    float acc = 0.0f;
    #pragma unroll
    for (int l = 0; l < LL; l++) {
        acc = fmaf(ws[l], lt[(size_t)toks[l] * VD + t], acc);
    }
    dst[t] = acc;
}

// ---------------------------------------------------------------------------
// Block reduce helper (256 threads)
// ---------------------------------------------------------------------------
__device__ __forceinline__ float block_reduce_sum_256(float v, float* sred)
{
    const int lane = threadIdx.x & 31;
    const int wid  = threadIdx.x >> 5;
    #pragma unroll
    for (int o = 16; o; o >>= 1) v += __shfl_xor_sync(0xFFFFFFFFu, v, o);
    if (lane == 0) sred[wid] = v;
    __syncthreads();
    float r = (threadIdx.x < 8) ? sred[threadIdx.x] : 0.0f;
    if (wid == 0) {
        #pragma unroll
        for (int o = 4; o; o >>= 1) r += __shfl_xor_sync(0xFFFFFFFFu, r, o);
        if (lane == 0) sred[0] = r;
    }
    __syncthreads();
    float res = sred[0];
    __syncthreads();
    return res;
}

// ---------------------------------------------------------------------------
// Kernel 2: cosine similarity of each mems_enc row vs xs_emb (row M).
// Grid: ROWS blocks x 256 threads.
// ---------------------------------------------------------------------------
__global__ void cos_kernel()
{
    __shared__ float sred[8];
    const int r = blockIdx.x;
    const int t = threadIdx.x;

    const float x = g_mems_enc[(size_t)MM * VD + t];
    const float m = g_mems_enc[(size_t)r  * VD + t];

    float dot = block_reduce_sum_256(m * x, sred);
    float mn  = block_reduce_sum_256(m * m, sred);
    float xn  = block_reduce_sum_256(x * x, sred);

    if (t == 0) {
        float an = fmaxf(sqrtf(xn), EPS);
        float bn = fmaxf(sqrtf(mn), EPS);
        g_cos[r] = dot / (an * bn);
    }
}

// ---------------------------------------------------------------------------
// Kernel 3: softmax over the ROWS cos values -> g_att. One block, 256 threads.
// ---------------------------------------------------------------------------
__global__ void softmax_kernel()
{
    __shared__ float sred[8];
    const int t = threadIdx.x;

    // max
    float m = -INFINITY;
    for (int r = t; r < ROWS; r += 256) m = fmaxf(m, g_cos[r]);
    {
        const int lane = t & 31, wid = t >> 5;
        #pragma unroll
        for (int o = 16; o; o >>= 1) m = fmaxf(m, __shfl_xor_sync(0xFFFFFFFFu, m, o));
        if (lane == 0) sred[wid] = m;
        __syncthreads();
        float mm = (t < 8) ? sred[t] : -INFINITY;
        if (wid == 0) {
            #pragma unroll
            for (int o = 4; o; o >>= 1) mm = fmaxf(mm, __shfl_xor_sync(0xFFFFFFFFu, mm, o));
            if (lane == 0) sred[0] = mm;
        }
        __syncthreads();
        m = sred[0];
        __syncthreads();
    }

    // sum of exp
    float s = 0.0f;
    for (int r = t; r < ROWS; r += 256) s += __expf(g_cos[r] - m);
    s = block_reduce_sum_256(s, sred);
    float inv = 1.0f / s;

    for (int r = t; r < ROWS; r += 256) g_att[r] = __expf(g_cos[r] - m) * inv;
}

// ---------------------------------------------------------------------------
// Kernel 4: partial att @ mems_enc. NPART blocks x 256 threads (deterministic).
// ---------------------------------------------------------------------------
__global__ void lhs_partial_kernel()
{
    const int t = threadIdx.x;
    float acc = 0.0f;
    for (int r = blockIdx.x; r < ROWS; r += NPART) {
        acc = fmaf(g_att[r], g_mems_enc[(size_t)r * VD + t], acc);
    }
    g_partial[blockIdx.x * VD + t] = acc;
}

// ---------------------------------------------------------------------------
// Kernel 5: reduce partials -> g_lhs. One block, 256 threads.
// ---------------------------------------------------------------------------
__global__ void lhs_final_kernel()
{
    const int t = threadIdx.x;
    float acc = 0.0f;
    #pragma unroll
    for (int b = 0; b < NPART; b++) acc += g_partial[b * VD + t];
    g_lhs[t] = acc;
}

// ---------------------------------------------------------------------------
// Kernel 6: tile g_lhs into xs_out (C+1 identical rows).
// Grid: C+1 blocks x 256 threads.
// ---------------------------------------------------------------------------
__global__ void tile_kernel(float* __restrict__ out_xs)
{
    out_xs[(size_t)blockIdx.x * VD + threadIdx.x] = g_lhs[threadIdx.x];
}

// ---------------------------------------------------------------------------
extern "C" void kernel_launch(void* const* d_in, const int* in_sizes, int n_in,
                              void* d_out, int out_size)
{
    const int*   xs    = (const int*)  d_in[0];
    const int*   mems  = (const int*)  d_in[1];
    const int*   ys    = (const int*)  d_in[2];
    const int*   cands = (const int*)  d_in[3];
    const float* lt    = (const float*)d_in[4];
    const float* freqs = (const float*)d_in[5];

    float* out    = (float*)d_out;
    float* out_xs = out;                          // [C+1, D]
    float* out_ys = out + (size_t)(CC + 1) * VD;  // [C+1, D]

    const int n_seq = MM + 2 + CC;  // mems, xs, ys, cands

    encode_kernel<<<n_seq, VD>>>(xs, mems, ys, cands, lt, freqs, out_ys);
    cos_kernel<<<ROWS, VD>>>();
    softmax_kernel<<<1, VD>>>();
    lhs_partial_kernel<<<NPART, VD>>>();
    lhs_final_kernel<<<1, VD>>>();
    tile_kernel<<<CC + 1, VD>>>(out_xs);
}